// round 2
// baseline (speedup 1.0000x reference)
#include <cuda_runtime.h>

#define CCH 64          // channels
#define CO 8            // q/k channels (C/8)
#define WIN 13          // window
#define WPB 8           // windows per block
#define TP 104          // voxels per tile = WPB*WIN
#define TPP 108         // padded row (bank-conflict-free, /4 for float4 stores)
#define NTHREADS 256
#define NVOX 53248      // D*H*W = 13*64*64
#define NB (NVOX / WIN) // 4096 windows per batch
#define TILES_PER_B (NB / WPB) // 512

struct Smem {
    float xs[CCH][TPP];         // raw x tile
    float ys[CCH][TPP];         // x @ att^T
    float q[CO][TPP];
    float k[CO][TPP];
    float att[WPB][WIN * WIN];
    float wq[CO][CCH];
    float wk[CO][CCH];
    float wv[CCH][CCH];
    float bq[CO];
    float bk[CO];
    float bv[CCH];
};

__global__ __launch_bounds__(NTHREADS, 2)
void win_attn_kernel(const float* __restrict__ x,
                     const float* __restrict__ wq, const float* __restrict__ bq,
                     const float* __restrict__ wk, const float* __restrict__ bk,
                     const float* __restrict__ wv, const float* __restrict__ bv,
                     float* __restrict__ out) {
    extern __shared__ char smem_raw[];
    Smem& s = *reinterpret_cast<Smem*>(smem_raw);

    const int tid  = threadIdx.x;
    const int b    = blockIdx.x / TILES_PER_B;
    const int tile = blockIdx.x % TILES_PER_B;
    const long n0  = (long)tile * TP;

    const float* xb = x   + (long)b * CCH * NVOX + n0;
    float*       ob = out + (long)b * CCH * NVOX + n0;

    // ---- load weights/biases into shared ----
    for (int i = tid; i < CO * CCH; i += NTHREADS) {
        s.wq[0][i] = wq[i];
        s.wk[0][i] = wk[i];
    }
    for (int i = tid; i < CCH * CCH; i += NTHREADS)
        s.wv[0][i] = wv[i];
    if (tid < CO)  { s.bq[tid] = bq[tid]; s.bk[tid] = bk[tid]; }
    if (tid < CCH) s.bv[tid] = bv[tid];

    // ---- load x tile: 64 rows x 104 floats, vec4 coalesced ----
    for (int i = tid; i < CCH * (TP / 4); i += NTHREADS) {
        int r  = i / (TP / 4);
        int c4 = i % (TP / 4);
        float4 v = *reinterpret_cast<const float4*>(xb + (long)r * NVOX + c4 * 4);
        s.xs[r][c4 * 4 + 0] = v.x;
        s.xs[r][c4 * 4 + 1] = v.y;
        s.xs[r][c4 * 4 + 2] = v.z;
        s.xs[r][c4 * 4 + 3] = v.w;
    }
    __syncthreads();

    // ---- q / k projections: 8 x 104 each ----
    for (int i = tid; i < CO * TP; i += NTHREADS) {
        int o = i / TP, p = i % TP;
        float aq = s.bq[o], ak = s.bk[o];
#pragma unroll
        for (int c = 0; c < CCH; c++) {
            float xv = s.xs[c][p];
            aq = fmaf(s.wq[o][c], xv, aq);
            ak = fmaf(s.wk[o][c], xv, ak);
        }
        s.q[o][p] = aq;
        s.k[o][p] = ak;
    }
    __syncthreads();

    // ---- scores: per window 13x13 over 8 q/k channels ----
    for (int i = tid; i < WPB * WIN * WIN; i += NTHREADS) {
        int w  = i / (WIN * WIN);
        int ij = i % (WIN * WIN);
        int ii = ij / WIN, jj = ij % WIN;
        float acc = 0.f;
#pragma unroll
        for (int o = 0; o < CO; o++)
            acc = fmaf(s.q[o][w * WIN + ii], s.k[o][w * WIN + jj], acc);
        s.att[w][ij] = acc;
    }
    __syncthreads();

    // ---- softmax over each of the 104 rows (length 13) ----
    for (int i = tid; i < TP; i += NTHREADS) {
        int w = i / WIN, ii = i % WIN;
        float* row = &s.att[w][ii * WIN];
        float m = row[0];
#pragma unroll
        for (int j = 1; j < WIN; j++) m = fmaxf(m, row[j]);
        float sum = 0.f;
#pragma unroll
        for (int j = 0; j < WIN; j++) {
            float e = __expf(row[j] - m);
            row[j] = e;
            sum += e;
        }
        float inv = __frcp_rn(sum);
#pragma unroll
        for (int j = 0; j < WIN; j++) row[j] *= inv;
    }
    __syncthreads();

    // ---- y = x . att^T  (apply attention to raw channels; valid since
    //      softmax rows sum to 1, so wv/bv commute through) ----
    for (int i = tid; i < CCH * TP; i += NTHREADS) {
        int c = i / TP, p = i % TP;
        int w = p / WIN, ii = p % WIN;
        const float* xr = &s.xs[c][w * WIN];
        const float* ar = &s.att[w][ii * WIN];
        float acc = 0.f;
#pragma unroll
        for (int j = 0; j < WIN; j++) acc = fmaf(xr[j], ar[j], acc);
        s.ys[c][p] = acc;
    }
    __syncthreads();

    // ---- out = wv @ y + bv, register tile: 2 channels x 13 positions ----
    const int ct = tid >> 3;          // 0..31
    const int pt = tid & 7;           // 0..7
    const int c0 = ct * 2;
    const int p0 = pt * WIN;

    float acc0[WIN], acc1[WIN];
    const float bv0 = s.bv[c0], bv1 = s.bv[c0 + 1];
#pragma unroll
    for (int j = 0; j < WIN; j++) { acc0[j] = bv0; acc1[j] = bv1; }

#pragma unroll 4
    for (int cc = 0; cc < CCH; cc++) {
        float w0 = s.wv[c0][cc];
        float w1 = s.wv[c0 + 1][cc];
        const float* yr = &s.ys[cc][p0];
#pragma unroll
        for (int j = 0; j < WIN; j++) {
            float yv = yr[j];
            acc0[j] = fmaf(w0, yv, acc0[j]);
            acc1[j] = fmaf(w1, yv, acc1[j]);
        }
    }

    float* o0 = ob + (long)c0 * NVOX + p0;
    float* o1 = o0 + NVOX;
#pragma unroll
    for (int j = 0; j < WIN; j++) { o0[j] = acc0[j]; o1[j] = acc1[j]; }
}

extern "C" void kernel_launch(void* const* d_in, const int* in_sizes, int n_in,
                              void* d_out, int out_size) {
    const float* x  = (const float*)d_in[0];
    const float* wq = (const float*)d_in[1];
    const float* bq = (const float*)d_in[2];
    const float* wk = (const float*)d_in[3];
    const float* bk = (const float*)d_in[4];
    const float* wv = (const float*)d_in[5];
    const float* bv = (const float*)d_in[6];
    float* out = (float*)d_out;

    const int B = in_sizes[0] / (CCH * NVOX);   // 8
    const int smem = (int)sizeof(Smem);

    static bool attr_set = false;
    if (!attr_set) {
        cudaFuncSetAttribute(win_attn_kernel,
                             cudaFuncAttributeMaxDynamicSharedMemorySize, smem);
        attr_set = true;
    }

    dim3 grid(B * TILES_PER_B);
    win_attn_kernel<<<grid, NTHREADS, smem>>>(x, wq, bq, wk, bk, wv, bv, out);
}

// round 3
// speedup vs baseline: 1.4581x; 1.4581x over previous
#include <cuda_runtime.h>

#define CCH 64          // channels
#define CO 8            // q/k channels (C/8)
#define WIN 13          // window size
#define WPB 8           // windows per block
#define TP 104          // voxels per tile
#define PADW 20         // per-window pitch in xs (bank-conflict-free for 8 windows)
#define XROW 160        // xs row length = WPB*PADW
#define ATTP 180        // att row pitch (20*w mod 32 distinct -> conflict-free broadcast)
#define WVP 66          // wvT row pitch (keeps float2 loads 8B-aligned, mild write conflicts only)
#define NTHREADS 256
#define NVOX 53248      // D*H*W
#define TILES_PER_B 512 // NVOX / TP

struct Smem {
    float xs[CCH][XROW];     // 40960 B  window-padded x tile
    float wvT[CCH][WVP];     // 16896 B  wv transposed [cc][c]
    float wqT[CCH][CO];      //  2048 B  wq transposed [c][o]
    float wkT[CCH][CO];      //  2048 B
    float qT[TP][CO];        //  3328 B  q transposed [p][o] (rows 32B aligned)
    float kT[TP][CO];        //  3328 B
    float att[WPB][ATTP];    //  5760 B
    float bqs[CO];
    float bks[CO];
    float bvs[CCH];
};

__global__ __launch_bounds__(NTHREADS, 3)
void win_attn_kernel(const float* __restrict__ x,
                     const float* __restrict__ wq, const float* __restrict__ bq,
                     const float* __restrict__ wk, const float* __restrict__ bk,
                     const float* __restrict__ wv, const float* __restrict__ bv,
                     float* __restrict__ out) {
    extern __shared__ char smem_raw[];
    Smem& s = *reinterpret_cast<Smem*>(smem_raw);

    const int tid  = threadIdx.x;
    const int b    = blockIdx.x / TILES_PER_B;
    const int tile = blockIdx.x % TILES_PER_B;
    const long n0  = (long)tile * TP;

    const float* xb = x   + (long)b * CCH * NVOX + n0;
    float*       ob = out + (long)b * CCH * NVOX + n0;

    // ---- weights (transposed) + biases into shared ----
    for (int i = tid; i < CO * CCH; i += NTHREADS) {
        int o = i / CCH, c = i % CCH;
        s.wqT[c][o] = wq[i];
        s.wkT[c][o] = wk[i];
    }
    for (int i = tid; i < CCH * CCH; i += NTHREADS) {
        int c = i / CCH, cc = i % CCH;
        s.wvT[cc][c] = wv[i];
    }
    if (tid < CO)                      s.bqs[tid]       = bq[tid];
    if (tid >= 64 && tid < 64 + CO)    s.bks[tid - 64]  = bk[tid - 64];
    if (tid >= 128 && tid < 128 + CCH) s.bvs[tid - 128] = bv[tid - 128];

    // ---- load x tile into window-padded smem layout ----
    for (int i = tid; i < CCH * (TP / 4); i += NTHREADS) {
        int r  = i / (TP / 4);
        int c4 = i % (TP / 4);
        float4 v = *reinterpret_cast<const float4*>(xb + (long)r * NVOX + c4 * 4);
        int p = c4 * 4;
        float vv[4] = {v.x, v.y, v.z, v.w};
#pragma unroll
        for (int u = 0; u < 4; u++) {
            int pp = p + u;
            s.xs[r][(pp / WIN) * PADW + (pp % WIN)] = vv[u];
        }
    }
    __syncthreads();

    // ---- q / k projection: item = (o-block of 4, real position), 208 items ----
    for (int m = tid; m < 2 * TP; m += NTHREADS) {
        int o4  = m / TP;            // 0 or 1 -> channels o4*4 .. o4*4+3
        int r   = m % TP;
        int col = (r / WIN) * PADW + (r % WIN);
        float aq0 = s.bqs[o4 * 4 + 0], aq1 = s.bqs[o4 * 4 + 1];
        float aq2 = s.bqs[o4 * 4 + 2], aq3 = s.bqs[o4 * 4 + 3];
        float ak0 = s.bks[o4 * 4 + 0], ak1 = s.bks[o4 * 4 + 1];
        float ak2 = s.bks[o4 * 4 + 2], ak3 = s.bks[o4 * 4 + 3];
#pragma unroll 8
        for (int c = 0; c < CCH; c++) {
            float  xv = s.xs[c][col];
            float4 q4 = *reinterpret_cast<const float4*>(&s.wqT[c][o4 * 4]);
            float4 k4 = *reinterpret_cast<const float4*>(&s.wkT[c][o4 * 4]);
            aq0 = fmaf(q4.x, xv, aq0); aq1 = fmaf(q4.y, xv, aq1);
            aq2 = fmaf(q4.z, xv, aq2); aq3 = fmaf(q4.w, xv, aq3);
            ak0 = fmaf(k4.x, xv, ak0); ak1 = fmaf(k4.y, xv, ak1);
            ak2 = fmaf(k4.z, xv, ak2); ak3 = fmaf(k4.w, xv, ak3);
        }
        *reinterpret_cast<float4*>(&s.qT[r][o4 * 4]) = make_float4(aq0, aq1, aq2, aq3);
        *reinterpret_cast<float4*>(&s.kT[r][o4 * 4]) = make_float4(ak0, ak1, ak2, ak3);
    }
    __syncthreads();

    // ---- scores: 8 windows x 13x13, dot over 8 q/k channels ----
    for (int m = tid; m < WPB * WIN * WIN; m += NTHREADS) {
        int w  = m / (WIN * WIN);
        int ij = m % (WIN * WIN);
        int ii = ij / WIN, jj = ij % WIN;
        float4 qa = *reinterpret_cast<const float4*>(&s.qT[w * WIN + ii][0]);
        float4 qb = *reinterpret_cast<const float4*>(&s.qT[w * WIN + ii][4]);
        float4 ka = *reinterpret_cast<const float4*>(&s.kT[w * WIN + jj][0]);
        float4 kb = *reinterpret_cast<const float4*>(&s.kT[w * WIN + jj][4]);
        float acc = qa.x * ka.x + qa.y * ka.y + qa.z * ka.z + qa.w * ka.w
                  + qb.x * kb.x + qb.y * kb.y + qb.z * kb.z + qb.w * kb.w;
        s.att[w][ij] = acc;
    }
    __syncthreads();

    // ---- softmax over 104 rows of length 13 ----
    if (tid < TP) {
        int w = tid / WIN, ii = tid % WIN;
        float* row = &s.att[w][ii * WIN];
        float m0 = row[0];
#pragma unroll
        for (int j = 1; j < WIN; j++) m0 = fmaxf(m0, row[j]);
        float sum = 0.f;
#pragma unroll
        for (int j = 0; j < WIN; j++) {
            float e = __expf(row[j] - m0);
            row[j] = e;
            sum += e;
        }
        float inv = __frcp_rn(sum);
#pragma unroll
        for (int j = 0; j < WIN; j++) row[j] *= inv;
    }
    __syncthreads();

    // ---- fused: z = wv @ x (register tile 2ch x 13pos), then out = z.att^T + bv ----
    {
        const int ct = tid >> 3;       // 0..31 -> channel pair
        const int pt = tid & 7;        // 0..7  -> window
        const int c0 = ct * 2;
        const int col0 = pt * PADW;

        float z0[WIN], z1[WIN];
#pragma unroll
        for (int j = 0; j < WIN; j++) { z0[j] = 0.f; z1[j] = 0.f; }

#pragma unroll 4
        for (int cc = 0; cc < CCH; cc++) {
            const float* xr = &s.xs[cc][col0];
            float4 xa = *reinterpret_cast<const float4*>(xr);
            float4 xm = *reinterpret_cast<const float4*>(xr + 4);
            float4 xc = *reinterpret_cast<const float4*>(xr + 8);
            float  xd = xr[12];
            float2 wv2 = *reinterpret_cast<const float2*>(&s.wvT[cc][c0]);
            float xv[WIN] = {xa.x, xa.y, xa.z, xa.w,
                             xm.x, xm.y, xm.z, xm.w,
                             xc.x, xc.y, xc.z, xc.w, xd};
#pragma unroll
            for (int j = 0; j < WIN; j++) {
                z0[j] = fmaf(wv2.x, xv[j], z0[j]);
                z1[j] = fmaf(wv2.y, xv[j], z1[j]);
            }
        }

        const float* ar = &s.att[pt][0];
        const float bv0 = s.bvs[c0], bv1 = s.bvs[c0 + 1];
        float* o0 = ob + (long)c0 * NVOX + pt * WIN;
        float* o1 = o0 + NVOX;
#pragma unroll
        for (int i = 0; i < WIN; i++) {
            float s0 = 0.f, s1 = 0.f;
#pragma unroll
            for (int j = 0; j < WIN; j++) {
                float aij = ar[i * WIN + j];
                s0 = fmaf(z0[j], aij, s0);
                s1 = fmaf(z1[j], aij, s1);
            }
            o0[i] = s0 + bv0;
            o1[i] = s1 + bv1;
        }
    }
}

extern "C" void kernel_launch(void* const* d_in, const int* in_sizes, int n_in,
                              void* d_out, int out_size) {
    const float* x  = (const float*)d_in[0];
    const float* wq = (const float*)d_in[1];
    const float* bq = (const float*)d_in[2];
    const float* wk = (const float*)d_in[3];
    const float* bk = (const float*)d_in[4];
    const float* wv = (const float*)d_in[5];
    const float* bv = (const float*)d_in[6];
    float* out = (float*)d_out;

    const int B = in_sizes[0] / (CCH * NVOX);   // 8
    const int smem = (int)sizeof(Smem);

    static bool attr_set = false;
    if (!attr_set) {
        cudaFuncSetAttribute(win_attn_kernel,
                             cudaFuncAttributeMaxDynamicSharedMemorySize, smem);
        attr_set = true;
    }

    dim3 grid(B * TILES_PER_B);
    win_attn_kernel<<<grid, NTHREADS, smem>>>(x, wq, bq, wk, bk, wv, bv, out);
}